// round 7
// baseline (speedup 1.0000x reference)
#include <cuda_runtime.h>

// CharRNN: B=512, T=2048, VOCAB=96, EMBED=32, HIDDEN=128
// R6: cell kernel unchanged from R5. Decoder GEMM re-blocked:
//   CTA = 128 rows x 96 v, 256 threads, thread tile Mr=8 x Nr=6.
//   H row-pair packed u64 in smem (64KB), W duplicated (w,w) u64 (96KB).
//   Per k per thread: 4+6 LDS.64 feeding 24 FFMA2 -> fma-bound.

#define VOCABN 96
#define EMBEDN 32
#define HID    128
#define BATCH  512
#define TLEN   2048
#define BROWS  4
#define NBLK   (BATCH / BROWS)   // 128
#define CTHR   256               // cell kernel threads
#define WCS    (EMBEDN + HID)    // 160

#define KPAD   132               // padded u64 per row-pair (k -> k + (k>>5))
#define HP_BUF (2 * KPAD)
#define ETS    132               // padded Et row stride (floats)

typedef unsigned long long u64;

// 512 MB scratch for all hidden states: H[t][b][j]
__device__ float g_H[(size_t)TLEN * BATCH * HID];

__device__ __forceinline__ u64 ffma2(u64 a, u64 b, u64 c) {
    u64 d;
    asm("fma.rn.f32x2 %0, %1, %2, %3;" : "=l"(d) : "l"(a), "l"(b), "l"(c));
    return d;
}
__device__ __forceinline__ u64 fadd2(u64 a, u64 b) {
    u64 d;
    asm("add.rn.f32x2 %0, %1, %2;" : "=l"(d) : "l"(a), "l"(b));
    return d;
}
__device__ __forceinline__ u64 pack2(float x, float y) {
    u64 d;
    asm("mov.b64 %0, {%1, %2};" : "=l"(d) : "f"(x), "f"(y));
    return d;
}
__device__ __forceinline__ float2 unpack2(u64 a) {
    float2 r;
    asm("mov.b64 {%0, %1}, %2;" : "=f"(r.x), "=f"(r.y) : "l"(a));
    return r;
}
__device__ __forceinline__ u64 shflx64(u64 v, int m) {
    float2 p = unpack2(v);
    p.x = __shfl_xor_sync(0xffffffffu, p.x, m);
    p.y = __shfl_xor_sync(0xffffffffu, p.y, m);
    return pack2(p.x, p.y);
}
__device__ __forceinline__ float tanh_fast(float x) {
    float e;
    asm("ex2.approx.f32 %0, %1;" : "=f"(e) : "f"(x * 2.8853900817779268f));
    float r;
    asm("rcp.approx.f32 %0, %1;" : "=f"(r) : "f"(e + 1.0f));
    return fmaf(-2.0f, r, 1.0f);
}

// ---------------- cell-loop kernel (unchanged from R5) ----------------
#define F_ET 0
#define F_HP (F_ET + VOCABN*ETS)
#define F_XS (F_HP + 2*HP_BUF*2)
#define C_SMEM_FLOATS (F_XS + BROWS*TLEN)
#define C_SMEM_BYTES  (C_SMEM_FLOATS * 4)

__global__ void __launch_bounds__(CTHR, 1)
charrnn_cell_kernel(const int* __restrict__ x,
                    const float* __restrict__ h0,
                    const float* __restrict__ emb,
                    const float* __restrict__ Wcell,
                    const float* __restrict__ bcell,
                    float* __restrict__ hfin)
{
    extern __shared__ float smem[];
    float* Et  = smem + F_ET;
    u64*   hpU = (u64*)(smem + F_HP);
    int*   xs  = (int*)(smem + F_XS);

    const int tid = threadIdx.x;
    const int b0  = blockIdx.x * BROWS;

    const int s  = tid & 3;
    const int up = tid >> 2;
    const int j0 = 2 * up;
    const int jp = j0 + (j0 >> 5);
    const int sb = 33 * s;

    u64 wd0[32], wd1[32];
    {
        const float* r0p = Wcell + j0 * WCS + EMBEDN + s * 32;
        const float* r1p = r0p + WCS;
        #pragma unroll
        for (int k = 0; k < 32; k++) {
            float a = r0p[k], b = r1p[k];
            wd0[k] = pack2(a, a);
            wd1[k] = pack2(b, b);
        }
    }

    if (tid < HID) {
        const int j = tid;
        float we[EMBEDN];
        #pragma unroll
        for (int k = 0; k < EMBEDN; k++)
            we[k] = Wcell[j * WCS + k];
        const float bc = bcell[j];
        for (int vv = 0; vv < VOCABN; vv++) {
            float a = bc;
            #pragma unroll
            for (int k = 0; k < EMBEDN; k++)
                a = fmaf(emb[vv * EMBEDN + k], we[k], a);
            Et[vv * ETS + j] = a;
        }
    }

    for (int i = tid; i < BROWS * TLEN; i += CTHR) {
        int t = i >> 2, r = i & 3;
        xs[i] = x[(b0 + r) * TLEN + t];
    }

    {
        float a = h0[(b0 + s) * HID + j0];
        float b = h0[(b0 + s) * HID + j0 + 1];
        float* hpF = (float*)hpU;
        hpF[(s >> 1) * (2 * KPAD) + jp * 2 + (s & 1)]       = a;
        hpF[(s >> 1) * (2 * KPAD) + (jp + 1) * 2 + (s & 1)] = b;
    }
    __syncthreads();

    float th0 = 0.f, th1 = 0.f;

    #pragma unroll 1
    for (int t = 0; t < TLEN; t++) {
        const u64* h01 = hpU + (t & 1) * HP_BUF + sb;
        const u64* h23 = h01 + KPAD;
        u64 aX0 = 0, aY0 = 0, aX1 = 0, aY1 = 0;
        #pragma unroll
        for (int kk = 0; kk < 32; kk++) {
            u64 hA = h01[kk];
            u64 hB = h23[kk];
            aX0 = ffma2(hA, wd0[kk], aX0);
            aY0 = ffma2(hB, wd0[kk], aY0);
            aX1 = ffma2(hA, wd1[kk], aX1);
            aY1 = ffma2(hB, wd1[kk], aY1);
        }
        u64 k0 = (s & 2) ? aY0 : aX0;
        u64 g0 = (s & 2) ? aX0 : aY0;
        u64 k1 = (s & 2) ? aY1 : aX1;
        u64 g1 = (s & 2) ? aX1 : aY1;
        k0 = fadd2(k0, shflx64(g0, 2));
        k1 = fadd2(k1, shflx64(g1, 2));
        k0 = fadd2(k0, shflx64(k0, 1));
        k1 = fadd2(k1, shflx64(k1, 1));
        float2 q0 = unpack2(k0), q1 = unpack2(k1);
        float uj0 = (s & 1) ? q0.y : q0.x;
        float uj1 = (s & 1) ? q1.y : q1.x;
        const int xv = xs[t * 4 + s];
        const float2 et2 = *(const float2*)&Et[xv * ETS + j0];
        th0 = tanh_fast(uj0 + et2.x);
        th1 = tanh_fast(uj1 + et2.y);
        const int nb = (t + 1) & 1;
        float* hpF = (float*)(hpU + nb * HP_BUF);
        hpF[(s >> 1) * (2 * KPAD) + jp * 2 + (s & 1)]       = th0;
        hpF[(s >> 1) * (2 * KPAD) + (jp + 1) * 2 + (s & 1)] = th1;
        *(float2*)&g_H[((size_t)t * BATCH + (b0 + s)) * HID + j0] =
            make_float2(th0, th1);
        __syncthreads();
    }

    if (hfin)
        *(float2*)&hfin[(b0 + s) * HID + j0] = make_float2(th0, th1);
}

// ---------------- decoder GEMM kernel (R6 re-block) ----------------
// out[b][t][v] = H[t][b][:] . Wdec[v][:] + bdec[v]
// CTA: 128 rows x 96 v, 256 thr = 16 rowgroups (8 rows) x 16 vgroups (6 v,
// interleaved v = q*16+vg). Thread: Mr=8 x Nr=6 -> 24 u64 accs.
#define D_ROWS 128
#define D_THR  256

// smem (u64 units unless noted):
//  htp : 128 k * 64 rp  u64   (h_2rp, h_2rp+1)        = 64 KB
//  wtd : 128 k * 96 v   u64   (w, w)                   = 96 KB
//  bias: 96 floats
#define U_HTP  0
#define U_WTD  (U_HTP + 128*64)
#define U_END  (U_WTD + 128*96)
#define D_SMEM_BYTES (U_END * 8 + 96 * 4)

__global__ void __launch_bounds__(D_THR, 1)
charrnn_dec_kernel(const float* __restrict__ Wdec,   // [96][128]
                   const float* __restrict__ bdec,   // [96]
                   float* __restrict__ out)          // [512][2048][96]
{
    extern __shared__ u64 smemU[];
    u64*   htp  = smemU + U_HTP;
    u64*   wtd  = smemU + U_WTD;
    float* bias = (float*)(smemU + U_END);

    const int tid  = threadIdx.x;
    const size_t row0 = (size_t)blockIdx.x * D_ROWS;

    // ---- stage W duplicated: wtd[k*96+v] = (w,w) ----
    for (int i = tid; i < VOCABN * HID; i += D_THR) {
        int v = i % VOCABN;
        int k = i / VOCABN;
        float w = Wdec[v * HID + k];
        wtd[k * VOCABN + v] = pack2(w, w);
    }
    if (tid < VOCABN) bias[tid] = bdec[tid];

    // ---- stage H row-pair packed: htp[k*64+rp] = (h_2rp, h_2rp+1) ----
    {
        const int rp = tid & 63;
        const int kc = tid >> 6;          // k-chunk 0..3 (32 k each)
        const float4* p0 = (const float4*)&g_H[(row0 + 2 * rp) * HID + kc * 32];
        const float4* p1 = (const float4*)&g_H[(row0 + 2 * rp + 1) * HID + kc * 32];
        #pragma unroll
        for (int q = 0; q < 8; q++) {
            float4 a = p0[q];
            float4 b = p1[q];
            int k = kc * 32 + q * 4;
            htp[(k + 0) * 64 + rp] = pack2(a.x, b.x);
            htp[(k + 1) * 64 + rp] = pack2(a.y, b.y);
            htp[(k + 2) * 64 + rp] = pack2(a.z, b.z);
            htp[(k + 3) * 64 + rp] = pack2(a.w, b.w);
        }
    }
    __syncthreads();

    // ---- main loop: Mr=8 (4 row-pairs) x Nr=6 (v = q*16+vg) ----
    const int vg = tid & 15;
    const int rg = tid >> 4;

    u64 acc[4][6];
    #pragma unroll
    for (int i = 0; i < 4; i++)
        #pragma unroll
        for (int q = 0; q < 6; q++)
            acc[i][q] = 0ull;

    const u64* hB = htp + rg * 4;
    const u64* wB = wtd + vg;

    #pragma unroll 4
    for (int k = 0; k < HID; k++) {
        u64 h0 = hB[k * 64 + 0];
        u64 h1 = hB[k * 64 + 1];
        u64 h2 = hB[k * 64 + 2];
        u64 h3 = hB[k * 64 + 3];
        #pragma unroll
        for (int q = 0; q < 6; q++) {
            u64 wq = wB[k * VOCABN + q * 16];
            acc[0][q] = ffma2(h0, wq, acc[0][q]);
            acc[1][q] = ffma2(h1, wq, acc[1][q]);
            acc[2][q] = ffma2(h2, wq, acc[2][q]);
            acc[3][q] = ffma2(h3, wq, acc[3][q]);
        }
    }

    // ---- epilogue ----
    float bq[6];
    #pragma unroll
    for (int q = 0; q < 6; q++)
        bq[q] = bias[q * 16 + vg];

    #pragma unroll
    for (int i = 0; i < 4; i++) {
        const size_t ra = row0 + rg * 8 + 2 * i;     // = t*512 + b
        const size_t rb = ra + 1;
        const size_t ta = ra >> 9, ba = ra & 511;
        const size_t tb = rb >> 9, bb = rb & 511;
        float* oa = out + (ba * TLEN + ta) * VOCABN + vg;
        float* ob = out + (bb * TLEN + tb) * VOCABN + vg;
        #pragma unroll
        for (int q = 0; q < 6; q++) {
            float2 p = unpack2(acc[i][q]);
            oa[q * 16] = p.x + bq[q];
            ob[q * 16] = p.y + bq[q];
        }
    }
}

extern "C" void kernel_launch(void* const* d_in, const int* in_sizes, int n_in,
                              void* d_out, int out_size)
{
    const int*   x     = (const int*)d_in[0];
    const float* h0    = (const float*)d_in[1];
    const float* emb   = (const float*)d_in[2];
    const float* Wcell = (const float*)d_in[3];
    const float* bcell = (const float*)d_in[4];
    const float* Wdec  = (const float*)d_in[5];
    const float* bdec  = (const float*)d_in[6];

    float* out = (float*)d_out;
    const long long outs_elems = (long long)BATCH * TLEN * VOCABN;
    float* hfin = nullptr;
    if ((long long)out_size >= outs_elems + (long long)BATCH * HID)
        hfin = out + outs_elems;

    cudaFuncSetAttribute(charrnn_cell_kernel,
                         cudaFuncAttributeMaxDynamicSharedMemorySize, C_SMEM_BYTES);
    cudaFuncSetAttribute(charrnn_dec_kernel,
                         cudaFuncAttributeMaxDynamicSharedMemorySize, D_SMEM_BYTES);

    charrnn_cell_kernel<<<NBLK, CTHR, C_SMEM_BYTES>>>(x, h0, emb, Wcell, bcell,
                                                      hfin);

    const int gblocks = (int)(((size_t)TLEN * BATCH) / D_ROWS);   // 8192
    charrnn_dec_kernel<<<gblocks, D_THR, D_SMEM_BYTES>>>(Wdec, bdec, out);
}

// round 8
// speedup vs baseline: 2.2380x; 2.2380x over previous
#include <cuda_runtime.h>

// CharRNN: B=512, T=2048, VOCAB=96, EMBED=32, HIDDEN=128
// R7: both kernels rebalanced around the real LDS model (wavefronts ~ bytes
// delivered to lanes, 128B/cyc/SM).
//  Cell: 128 CTAs x 256 thr; thread = (j-quad, k-eighth). Duplicated (w,w)
//        weights in regs (64 u64). Per k: 2 LDS.64 + 8 FFMA2 (LDS == fma).
//        8-lane reduce-scatter (xor 4,2,1). h row-pair packed + k-padded.
//        h_t streamed to g_H as packed u64 (rows 2rp,2rp+1).
//  Dec : 8192 CTAs x 128 thr, 2 CTAs/SM. Thread tile Mr=16 rows x Nr=6 v.
//        W scalar in smem (stride 97), packed (w,w) at use -> fma-bound.

#define VOCABN 96
#define EMBEDN 32
#define HID    128
#define BATCH  512
#define TLEN   2048
#define BROWS  4
#define NBLK   (BATCH / BROWS)   // 128
#define CTHR   256
#define WCS    (EMBEDN + HID)    // 160
#define ETS    132               // padded Et row stride (floats)

typedef unsigned long long u64;

// hidden states, row-pair packed: g_H[((t*256 + b/2)*128 + j)] = (h[2rp][j], h[2rp+1][j])
__device__ u64 g_H[(size_t)TLEN * (BATCH / 2) * HID];

__device__ __forceinline__ u64 ffma2(u64 a, u64 b, u64 c) {
    u64 d;
    asm("fma.rn.f32x2 %0, %1, %2, %3;" : "=l"(d) : "l"(a), "l"(b), "l"(c));
    return d;
}
__device__ __forceinline__ u64 fadd2(u64 a, u64 b) {
    u64 d;
    asm("add.rn.f32x2 %0, %1, %2;" : "=l"(d) : "l"(a), "l"(b));
    return d;
}
__device__ __forceinline__ u64 pack2(float x, float y) {
    u64 d;
    asm("mov.b64 %0, {%1, %2};" : "=l"(d) : "f"(x), "f"(y));
    return d;
}
__device__ __forceinline__ float2 unpack2(u64 a) {
    float2 r;
    asm("mov.b64 {%0, %1}, %2;" : "=f"(r.x), "=f"(r.y) : "l"(a));
    return r;
}
__device__ __forceinline__ u64 shflx64(u64 v, int m) {
    float2 p = unpack2(v);
    p.x = __shfl_xor_sync(0xffffffffu, p.x, m);
    p.y = __shfl_xor_sync(0xffffffffu, p.y, m);
    return pack2(p.x, p.y);
}
__device__ __forceinline__ float tanh_fast(float x) {
    float e;
    asm("ex2.approx.f32 %0, %1;" : "=f"(e) : "f"(x * 2.8853900817779268f));
    float r;
    asm("rcp.approx.f32 %0, %1;" : "=f"(r) : "f"(e + 1.0f));
    return fmaf(-2.0f, r, 1.0f);
}

// ---------------- cell kernel ----------------
// smem: Et[96][132] floats, hp: 2 buf x 2 rp x 136 u64 (k -> k + (k>>4)),
//       xs: 2048*4 ints
#define HP_RP   136
#define HP_BUF  (2 * HP_RP)                 // u64 per buffer
#define F_ET 0
#define F_HP (F_ET + VOCABN*ETS)            // floats; u64-aligned (12672*4 % 8 == 0)
#define F_XS (F_HP + 2*HP_BUF*2)
#define C_SMEM_FLOATS (F_XS + BROWS*TLEN)
#define C_SMEM_BYTES  (C_SMEM_FLOATS * 4)

__global__ void __launch_bounds__(CTHR, 1)
charrnn_cell_kernel(const int* __restrict__ x,
                    const float* __restrict__ h0,
                    const float* __restrict__ emb,
                    const float* __restrict__ Wcell,
                    const float* __restrict__ bcell,
                    float* __restrict__ hfin)
{
    extern __shared__ float smem[];
    float* Et  = smem + F_ET;
    u64*   hpU = (u64*)(smem + F_HP);
    int*   xs  = (int*)(smem + F_XS);

    const int tid = threadIdx.x;
    const int b0  = blockIdx.x * BROWS;

    const int s  = tid & 7;          // k-eighth (k in [16s, 16s+16))
    const int jq = tid >> 3;         // j-quad 0..31
    const int jb = jq * 4;

    // duplicated (w,w) weights: wd[jj][kk] for j = jb+jj, k = 16s+kk
    u64 wd[4][16];
    #pragma unroll
    for (int jj = 0; jj < 4; jj++) {
        const float* p = Wcell + (jb + jj) * WCS + EMBEDN + s * 16;
        #pragma unroll
        for (int kk = 0; kk < 16; kk++) {
            float w = p[kk];
            wd[jj][kk] = pack2(w, w);
        }
    }

    // Et table (threads 0..127)
    if (tid < HID) {
        const int j = tid;
        float we[EMBEDN];
        #pragma unroll
        for (int k = 0; k < EMBEDN; k++)
            we[k] = Wcell[j * WCS + k];
        const float bc = bcell[j];
        for (int vv = 0; vv < VOCABN; vv++) {
            float a = bc;
            #pragma unroll
            for (int k = 0; k < EMBEDN; k++)
                a = fmaf(emb[vv * EMBEDN + k], we[k], a);
            Et[vv * ETS + j] = a;
        }
    }

    // token prefetch: xs[t*4 + r] = x[(b0+r)*T + t]
    for (int i = tid; i < BROWS * TLEN; i += CTHR) {
        int t = i >> 2, r = i & 3;
        xs[i] = x[(b0 + r) * TLEN + t];
    }

    // initial h -> buffer 0 (row-pair packed, padded): tid = rp*128 + j
    {
        const int rp = tid >> 7;
        const int jj = tid & 127;
        u64 v = pack2(h0[(b0 + 2 * rp) * HID + jj],
                      h0[(b0 + 2 * rp + 1) * HID + jj]);
        hpU[rp * HP_RP + jj + (jj >> 4)] = v;
    }
    __syncthreads();

    const int rp   = s >> 2;               // my output row-pair
    const int jfin = jb + (s & 3);         // my output hidden index
    const int jfp  = jfin + (jfin >> 4);   // padded
    const size_t gbase = (size_t)(b0 >> 1) + rp;   // row-pair row in g_H (per t: +256)
    float th0 = 0.f, th1 = 0.f;

    #pragma unroll 1
    for (int t = 0; t < TLEN; t++) {
        const u64* hb  = hpU + (t & 1) * HP_BUF;
        const u64* h0p = hb + 17 * s;          // rp 0, my k-slice (padded base)
        const u64* h1p = h0p + HP_RP;          // rp 1

        u64 a0[4] = {0, 0, 0, 0};
        u64 a1[4] = {0, 0, 0, 0};
        #pragma unroll
        for (int kk = 0; kk < 16; kk++) {
            u64 hA = h0p[kk];
            u64 hB = h1p[kk];
            #pragma unroll
            for (int jj = 0; jj < 4; jj++) {
                a0[jj] = ffma2(hA, wd[jj][kk], a0[jj]);
                a1[jj] = ffma2(hB, wd[jj][kk], a1[jj]);
            }
        }

        // reduce-scatter across 8 k-slices
        u64 kp4[4];
        #pragma unroll
        for (int jj = 0; jj < 4; jj++) {
            u64 keep = (s & 4) ? a1[jj] : a0[jj];
            u64 give = (s & 4) ? a0[jj] : a1[jj];
            kp4[jj] = fadd2(keep, shflx64(give, 4));
        }
        u64 kA = (s & 2) ? kp4[2] : kp4[0];
        u64 gA = (s & 2) ? kp4[0] : kp4[2];
        kA = fadd2(kA, shflx64(gA, 2));
        u64 kB = (s & 2) ? kp4[3] : kp4[1];
        u64 gB = (s & 2) ? kp4[1] : kp4[3];
        kB = fadd2(kB, shflx64(gB, 2));
        u64 kk2 = (s & 1) ? kB : kA;
        u64 gg  = (s & 1) ? kA : kB;
        kk2 = fadd2(kk2, shflx64(gg, 1));

        // finalize: rows (2rp, 2rp+1) at hidden index jfin
        const int i0 = xs[t * 4 + 2 * rp];
        const int i1 = xs[t * 4 + 2 * rp + 1];
        float2 u = unpack2(kk2);
        th0 = tanh_fast(u.x + Et[i0 * ETS + jfin]);
        th1 = tanh_fast(u.y + Et[i1 * ETS + jfin]);
        u64 hv = pack2(th0, th1);

        hpU[((t + 1) & 1) * HP_BUF + rp * HP_RP + jfp] = hv;
        g_H[((size_t)t * (BATCH / 2) + gbase) * HID + jfin] = hv;
        __syncthreads();
    }

    if (hfin) {
        hfin[(b0 + 2 * rp) * HID + jfin]     = th0;
        hfin[(b0 + 2 * rp + 1) * HID + jfin] = th1;
    }
}

// ---------------- decoder GEMM kernel ----------------
// out[b][t][v] = H[t][b][:] . Wdec[v][:] + bdec[v]
// CTA: 128 rows (64 rp) x 96 v, 128 thr = 8 rg x 16 vg. Thread: Mr=16 x Nr=6.
#define D_ROWS 128
#define D_THR  128
#define WS_S   97                           // padded W smem row stride (floats)

// smem: htp u64[128][64] = 64KB; ws float[128][97] = 48.5KB; bias 96 floats
#define U_HTP  0
#define U_END  (U_HTP + 128*64)             // u64 units
#define D_WS_OFF   (U_END * 2)              // float index of ws
#define D_BIAS_OFF (D_WS_OFF + 128*WS_S)
#define D_SMEM_FLOATS (D_BIAS_OFF + 96)
#define D_SMEM_BYTES  (D_SMEM_FLOATS * 4)

__global__ void __launch_bounds__(D_THR, 2)
charrnn_dec_kernel(const float* __restrict__ Wdec,   // [96][128]
                   const float* __restrict__ bdec,   // [96]
                   float* __restrict__ out)          // [512][2048][96]
{
    extern __shared__ u64 smemU[];
    u64*   htp  = smemU + U_HTP;                     // [k][rp]
    float* ws   = (float*)smemU + D_WS_OFF;          // [k][97] scalar W
    float* bias = (float*)smemU + D_BIAS_OFF;

    const int tid = threadIdx.x;
    // tile: rows rr0..rr0+127 where rr = t*512 + b  (t fixed within tile)
    const int t_idx = blockIdx.x >> 2;
    const int bb0   = (blockIdx.x & 3) * D_ROWS;
    const size_t rpg0 = (size_t)t_idx * (BATCH / 2) + (bb0 >> 1);

    // stage W scalar: ws[k*97 + v] = Wdec[v][k]
    for (int i = tid; i < VOCABN * HID; i += D_THR) {
        int v = i >> 7, k = i & 127;
        ws[k * WS_S + v] = Wdec[i];
    }
    if (tid < VOCABN) bias[tid] = bdec[tid];

    // stage H: htp[k][rp] = g_H[rpg0 + rp][k]  (already row-pair packed)
    {
        const int rp   = tid >> 1;
        const int half = tid & 1;
        const u64* src = g_H + (rpg0 + rp) * HID + half * 64;
        #pragma unroll
        for (int q = 0; q < 64; q++)
            htp[(half * 64 + q) * 64 + rp] = src[q];
    }
    __syncthreads();

    const int vg = tid & 15;
    const int rg = tid >> 4;
    const int v0 = vg * 6;

    u64 acc[8][6];
    #pragma unroll
    for (int i = 0; i < 8; i++)
        #pragma unroll
        for (int q = 0; q < 6; q++)
            acc[i][q] = 0ull;

    const u64*   hB = htp + rg * 8;
    const float* wB = ws + v0;

    #pragma unroll 4
    for (int k = 0; k < HID; k++) {
        u64 h[8];
        const ulonglong2* hp2 = (const ulonglong2*)(hB + k * 64);
        #pragma unroll
        for (int p = 0; p < 4; p++) {
            ulonglong2 hv = hp2[p];
            h[2 * p]     = hv.x;
            h[2 * p + 1] = hv.y;
        }
        #pragma unroll
        for (int q = 0; q < 6; q++) {
            float w = wB[k * WS_S + q];
            u64 w2 = pack2(w, w);
            #pragma unroll
            for (int i = 0; i < 8; i++)
                acc[i][q] = ffma2(h[i], w2, acc[i][q]);
        }
    }

    // epilogue
    float bq[6];
    #pragma unroll
    for (int q = 0; q < 6; q++)
        bq[q] = bias[v0 + q];

    #pragma unroll
    for (int i = 0; i < 8; i++) {
        const int rpl = rg * 8 + i;
        const int be  = bb0 + 2 * rpl;        // even batch row
        float* oe = out + ((size_t)be * TLEN + t_idx) * VOCABN + v0;
        float* oo = oe + (size_t)TLEN * VOCABN;
        float fe[6], fo[6];
        #pragma unroll
        for (int q = 0; q < 6; q++) {
            float2 p = unpack2(acc[i][q]);
            fe[q] = p.x + bq[q];
            fo[q] = p.y + bq[q];
        }
        #pragma unroll
        for (int q = 0; q < 3; q++) {
            *(float2*)(oe + 2 * q) = make_float2(fe[2 * q], fe[2 * q + 1]);
            *(float2*)(oo + 2 * q) = make_float2(fo[2 * q], fo[2 * q + 1]);
        }
    }
}

extern "C" void kernel_launch(void* const* d_in, const int* in_sizes, int n_in,
                              void* d_out, int out_size)
{
    const int*   x     = (const int*)d_in[0];
    const float* h0    = (const float*)d_in[1];
    const float* emb   = (const float*)d_in[2];
    const float* Wcell = (const float*)d_in[3];
    const float* bcell = (const float*)d_in[4];
    const float* Wdec  = (const float*)d_in[5];
    const float* bdec  = (const float*)d_in[6];

    float* out = (float*)d_out;
    const long long outs_elems = (long long)BATCH * TLEN * VOCABN;
    float* hfin = nullptr;
    if ((long long)out_size >= outs_elems + (long long)BATCH * HID)
        hfin = out + outs_elems;

    cudaFuncSetAttribute(charrnn_cell_kernel,
                         cudaFuncAttributeMaxDynamicSharedMemorySize, C_SMEM_BYTES);
    cudaFuncSetAttribute(charrnn_dec_kernel,
                         cudaFuncAttributeMaxDynamicSharedMemorySize, D_SMEM_BYTES);

    charrnn_cell_kernel<<<NBLK, CTHR, C_SMEM_BYTES>>>(x, h0, emb, Wcell, bcell,
                                                      hfin);

    const int gblocks = (int)(((size_t)TLEN * BATCH) / D_ROWS);   // 8192
    charrnn_dec_kernel<<<gblocks, D_THR, D_SMEM_BYTES>>>(Wdec, bdec, out);
}